// round 10
// baseline (speedup 1.0000x reference)
#include <cuda_runtime.h>
#include <cuda_fp16.h>
#include <cstdint>

// out[i,j] = exp(-(||H1_i||^2 + ||H2_j||^2 - 2*H1_i.H2_j)),  H1,H2: [8192,64] f32.
//
// Round 10: R9 minus its overhead.
//  - B rows permuted inside each 32-row group of the prep image so each lane's
//    MMA accumulator columns are contiguous (8t..8t+7): kills the xor(1)
//    shuffles + selects in the epilogue. xor(16) row-merge retained (4wf STGs).
//  - Tile loads via cp.async.bulk (TMA) + mbarrier: zero LSU wavefronts.

#define NR    8192
#define KDIM  64
#define TM    128
#define TN    128
#define LOG2E 1.4426950408889634f

// ---- device scratch: fp16 row images, 128-row blocks of 16KB, pre-swizzled ----
__device__ __align__(1024) uint8_t g_H1s[(size_t)NR * 128];
__device__ __align__(1024) uint8_t g_H2s[(size_t)NR * 128];
__device__ float g_norm1[NR];
__device__ float g_norm2[NR];

// ============================ PTX helpers ============================
__device__ __forceinline__ uint32_t smem_u32(const void* p) {
    uint32_t a;
    asm("{ .reg .u64 t; cvta.to.shared.u64 t, %1; cvt.u32.u64 %0, t; }" : "=r"(a) : "l"(p));
    return a;
}
__device__ __forceinline__ float ex2f(float x) {
    float y; asm("ex2.approx.ftz.f32 %0, %1;" : "=f"(y) : "f"(x)); return y;
}
__device__ __forceinline__ void ldsm_x4(uint32_t& r0, uint32_t& r1, uint32_t& r2, uint32_t& r3,
                                        uint32_t addr) {
    asm volatile("ldmatrix.sync.aligned.m8n8.x4.shared.b16 {%0,%1,%2,%3}, [%4];"
                 : "=r"(r0), "=r"(r1), "=r"(r2), "=r"(r3) : "r"(addr));
}
__device__ __forceinline__ void mma16816(float& c0, float& c1, float& c2, float& c3,
                                         uint32_t a0, uint32_t a1, uint32_t a2, uint32_t a3,
                                         uint32_t b0, uint32_t b1) {
    asm volatile(
        "mma.sync.aligned.m16n8k16.row.col.f32.f16.f16.f32 "
        "{%0,%1,%2,%3}, {%4,%5,%6,%7}, {%8,%9}, {%0,%1,%2,%3};"
        : "+f"(c0), "+f"(c1), "+f"(c2), "+f"(c3)
        : "r"(a0), "r"(a1), "r"(a2), "r"(a3), "r"(b0), "r"(b1));
}
#define MBAR_INIT(mbar, cnt) \
    asm volatile("mbarrier.init.shared.b64 [%0], %1;" :: "r"((uint32_t)(mbar)), "r"((uint32_t)(cnt)) : "memory")
#define MBAR_EXPECT_TX(mbar, bytes) \
    asm volatile("mbarrier.arrive.expect_tx.shared.b64 _, [%0], %1;" \
                 :: "r"((uint32_t)(mbar)), "r"((uint32_t)(bytes)) : "memory")
#define BULK_G2S(dst, src, bytes, mbar) \
    asm volatile("cp.async.bulk.shared::cta.global.mbarrier::complete_tx::bytes [%0], [%1], %2, [%3];" \
                 :: "r"((uint32_t)(dst)), "l"(src), "r"((uint32_t)(bytes)), "r"((uint32_t)(mbar)) : "memory")
__device__ __forceinline__ void mbar_wait(uint32_t mbar, uint32_t parity) {
    asm volatile(
        "{\n\t.reg .pred P;\n\t"
        "W%=:\n\t"
        "mbarrier.try_wait.parity.acquire.cta.shared::cta.b64 P, [%0], %1, 0x989680;\n\t"
        "@P bra.uni D%=;\n\t"
        "bra.uni W%=;\n\t"
        "D%=:\n\t}"
        :: "r"(mbar), "r"(parity) : "memory");
}

// ============================ pre-kernel ============================
__global__ void prep_kernel(const float* __restrict__ H1, const float* __restrict__ H2, int n1) {
    int gid = blockIdx.x * blockDim.x + threadIdx.x;
    int row = gid >> 4;
    int q   = gid & 15;                 // float4 chunk: k = 4q..4q+3
    bool isA = row < n1;
    int r = isA ? row : row - n1;
    const float* src = isA ? H1 : H2;
    float4 v = reinterpret_cast<const float4*>(src)[(size_t)r * 16 + q];

    float x[4] = {v.x, v.y, v.z, v.w};
    uint32_t hu[4];
    float ss = 0.f;
    #pragma unroll
    for (int e = 0; e < 4; e++) {
        hu[e] = (uint32_t)__half_as_ushort(__float2half_rn(x[e]));
        ss = fmaf(x[e], x[e], ss);
    }
    uint2 hi = make_uint2(hu[0] | (hu[1] << 16), hu[2] | (hu[3] << 16));

    int ib = r >> 7, lr = r & 127;
    if (!isA) {
        // permute within each 32-row group: actual a -> logical l so that the
        // MMA fragment columns of lane t are actual columns 8t..8t+7.
        int a = lr & 31;
        int l = (((a >> 1) & 3) << 3) | (((a >> 3) & 3) << 1) | (a & 1);
        lr = (lr & ~31) | l;
    }
    int chunk = q >> 1;
    int swc = chunk ^ (lr & 7);               // XOR swizzle for ldmatrix
    size_t off = (size_t)ib * 16384 + (size_t)lr * 128 + swc * 16 + (q & 1) * 8;
    uint8_t* base = isA ? g_H1s : g_H2s;
    *reinterpret_cast<uint2*>(base + off) = hi;

    #pragma unroll
    for (int o = 8; o; o >>= 1) ss += __shfl_xor_sync(0xffffffffu, ss, o, 16);
    if (q == 0) (isA ? g_norm1 : g_norm2)[r] = ss;   // norms in ACTUAL order
}

// ============================ main kernel ============================
#define SM_A    0
#define SM_B    16384
#define SM_N1   32768
#define SM_N2   33280
#define SM_MBAR 33792
#define SM_TOT  33920

__global__ __launch_bounds__(256, 2) void gk_mma(float* __restrict__ out) {
    extern __shared__ uint8_t smem[];
    const uint32_t sb = smem_u32(smem);
    const int tid  = threadIdx.x;
    const int wid  = tid >> 5;
    const int lane = tid & 31;
    const int iT = blockIdx.y * TM;
    const int jT = blockIdx.x * TN;

    // ---- TMA bulk copy of pre-swizzled tile images (16KB + 16KB) ----
    if (tid == 0) MBAR_INIT(sb + SM_MBAR, 1);
    __syncthreads();
    if (tid == 0) {
        MBAR_EXPECT_TX(sb + SM_MBAR, 32768u);
        BULK_G2S(sb + SM_A, g_H1s + (size_t)blockIdx.y * 16384, 16384u, sb + SM_MBAR);
        BULK_G2S(sb + SM_B, g_H2s + (size_t)blockIdx.x * 16384, 16384u, sb + SM_MBAR);
    }
    if (tid < 128) {
        ((float*)(smem + SM_N1))[tid] = g_norm1[iT + tid] * LOG2E;
        ((float*)(smem + SM_N2))[tid] = g_norm2[jT + tid] * LOG2E;
    }
    __syncthreads();                    // norms visible to all
    mbar_wait(sb + SM_MBAR, 0);         // TMA tiles visible (acquire)

    // warp tile: 64 rows x 32 cols.  wr in {0,1}, wc in {0..3}
    const int wr = wid & 1;
    const int wc = wid >> 1;

    float acc[4][4][4];                 // [mi][ni][frag]
    #pragma unroll
    for (int i = 0; i < 4; i++)
        #pragma unroll
        for (int j = 0; j < 4; j++)
            #pragma unroll
            for (int f = 0; f < 4; f++) acc[i][j][f] = 0.f;

    // ldmatrix lane addressing
    uint32_t aRow[4], aXor[4], aKbit = (uint32_t)(lane >> 4);
    #pragma unroll
    for (int mi = 0; mi < 4; mi++) {
        int ra = wr * 64 + mi * 16 + (lane & 15);
        aRow[mi] = sb + SM_A + ra * 128;
        aXor[mi] = (uint32_t)(ra & 7);
    }
    uint32_t bRow[2], bXor[2], bKbit = (uint32_t)((lane >> 3) & 1);
    #pragma unroll
    for (int ng = 0; ng < 2; ng++) {
        int nb = wc * 32 + ng * 16 + (lane & 7) + ((lane >> 4) & 1) * 8;
        bRow[ng] = sb + SM_B + nb * 128;
        bXor[ng] = (uint32_t)(nb & 7);
    }

    // Single term: per kc, 4 A-LDSM + 2 B-LDSM -> 16 HMMA.
    #pragma unroll
    for (int kc = 0; kc < 4; kc++) {
        uint32_t aF[4][4], bF[2][4];
        #pragma unroll
        for (int mi = 0; mi < 4; mi++) {
            uint32_t ch = (2u * kc + aKbit) ^ aXor[mi];
            ldsm_x4(aF[mi][0], aF[mi][1], aF[mi][2], aF[mi][3], aRow[mi] + (ch << 4));
        }
        #pragma unroll
        for (int ng = 0; ng < 2; ng++) {
            uint32_t ch = (2u * kc + bKbit) ^ bXor[ng];
            ldsm_x4(bF[ng][0], bF[ng][1], bF[ng][2], bF[ng][3], bRow[ng] + (ch << 4));
        }
        #pragma unroll
        for (int mi = 0; mi < 4; mi++)
            #pragma unroll
            for (int ni = 0; ni < 4; ni++)
                mma16816(acc[mi][ni][0], acc[mi][ni][1], acc[mi][ni][2], acc[mi][ni][3],
                         aF[mi][0], aF[mi][1], aF[mi][2], aF[mi][3],
                         bF[ni >> 1][(ni & 1) * 2], bF[ni >> 1][(ni & 1) * 2 + 1]);
    }

    // ---- epilogue: lane's 8 values are contiguous cols 8t..8t+7 of row lr0 ----
    const float* n1c = (const float*)(smem + SM_N1);
    const float* n2c = (const float*)(smem + SM_N2);
    const int t  = lane & 3;            // column sub-id (8-col group)
    const int g  = lane >> 2;           // row sub-id 0..7
    const bool hi_g = (g >= 4);
    const int  gl   = g & 3;
    const int colb = wc * 32 + t * 8;

    // column norms for this lane: n2c[colb .. colb+7]
    float cnv[8];
    #pragma unroll
    for (int j = 0; j < 8; j++) cnv[j] = n2c[colb + j];

    #pragma unroll
    for (int mi = 0; mi < 4; mi++) {
        int lr0 = wr * 64 + mi * 16 + g;
        float rnA = n1c[lr0];
        float rnB = n1c[lr0 + 8];

        #pragma unroll
        for (int half = 0; half < 2; half++) {
            float rn = half ? rnB : rnA;
            // value j (=2*ni+p) -> acc[mi][ni][half*2+p], actual col colb+j
            float4 w0, w1;
            w0.x = ex2f(fmaf(acc[mi][0][half * 2 + 0], 2.f * LOG2E, -rn) - cnv[0]);
            w0.y = ex2f(fmaf(acc[mi][0][half * 2 + 1], 2.f * LOG2E, -rn) - cnv[1]);
            w0.z = ex2f(fmaf(acc[mi][1][half * 2 + 0], 2.f * LOG2E, -rn) - cnv[2]);
            w0.w = ex2f(fmaf(acc[mi][1][half * 2 + 1], 2.f * LOG2E, -rn) - cnv[3]);
            w1.x = ex2f(fmaf(acc[mi][2][half * 2 + 0], 2.f * LOG2E, -rn) - cnv[4]);
            w1.y = ex2f(fmaf(acc[mi][2][half * 2 + 1], 2.f * LOG2E, -rn) - cnv[5]);
            w1.z = ex2f(fmaf(acc[mi][3][half * 2 + 0], 2.f * LOG2E, -rn) - cnv[6]);
            w1.w = ex2f(fmaf(acc[mi][3][half * 2 + 1], 2.f * LOG2E, -rn) - cnv[7]);

            // xor(16): swap w1 between g and g^4 partners -> each STG covers
            // 4 complete 128B rows (4 wavefronts).
            float4 w1x;
            w1x.x = __shfl_xor_sync(0xffffffffu, w1.x, 16);
            w1x.y = __shfl_xor_sync(0xffffffffu, w1.y, 16);
            w1x.z = __shfl_xor_sync(0xffffffffu, w1.z, 16);
            w1x.w = __shfl_xor_sync(0xffffffffu, w1.w, 16);

            const int Rbase = iT + wr * 64 + mi * 16 + half * 8;
            {   // rows Rbase..Rbase+3
                float4 v = hi_g ? w1x : w0;
                int col = colb + (hi_g ? 4 : 0);
                __stcs(reinterpret_cast<float4*>(out + (size_t)(Rbase + gl) * NR + jT + col), v);
            }
            {   // rows Rbase+4..Rbase+7
                float4 v = hi_g ? w0 : w1x;
                int col = colb + (hi_g ? 0 : 4);
                __stcs(reinterpret_cast<float4*>(out + (size_t)(Rbase + gl + 4) * NR + jT + col), v);
            }
        }
    }
}

// ============================ launch ============================
extern "C" void kernel_launch(void* const* d_in, const int* in_sizes, int n_in,
                              void* d_out, int out_size)
{
    const float* H1 = (const float*)d_in[0];
    const float* H2 = (const float*)d_in[1];
    float* out = (float*)d_out;

    int n1 = in_sizes[0] / KDIM;   // 8192
    int n2 = in_sizes[1] / KDIM;   // 8192

    prep_kernel<<<(n1 + n2) * 16 / 256, 256>>>(H1, H2, n1);

    static bool attr_set = false;
    if (!attr_set) {
        cudaFuncSetAttribute(gk_mma, cudaFuncAttributeMaxDynamicSharedMemorySize, SM_TOT);
        attr_set = true;
    }
    dim3 grid(n2 / TN, n1 / TM);   // (64, 64)
    gk_mma<<<grid, 256, SM_TOT>>>(out);
}

// round 11
// speedup vs baseline: 1.1576x; 1.1576x over previous
#include <cuda_runtime.h>
#include <cuda_fp16.h>
#include <cstdint>

// out[i,j] = exp(-(||H1_i||^2 + ||H2_j||^2 - 2*H1_i.H2_j)),  H1,H2: [8192,64] f32.
//
// Round 11: mi-wise pipelined mainloop. B fragments (all 4 kc) preloaded once;
// per mi: 4 A-LDSM + 16 HMMA -> 16 live accumulators -> immediate epilogue
// (exp2 + xor(16) row-merged 4-wavefront stores). Live regs drop from 64 acc
// to 16, enabling __launch_bounds__(256,3): 3 CTAs/SM, 24 warps, +50% latency
// hiding over R10's register-capped 2 CTAs.

#define NR    8192
#define KDIM  64
#define TM    128
#define TN    128
#define LOG2E 1.4426950408889634f

// ---- device scratch: fp16 row images, 128-row blocks of 16KB, pre-swizzled ----
__device__ __align__(1024) uint8_t g_H1s[(size_t)NR * 128];
__device__ __align__(1024) uint8_t g_H2s[(size_t)NR * 128];
__device__ float g_norm1[NR];
__device__ float g_norm2[NR];

// ============================ PTX helpers ============================
__device__ __forceinline__ uint32_t smem_u32(const void* p) {
    uint32_t a;
    asm("{ .reg .u64 t; cvta.to.shared.u64 t, %1; cvt.u32.u64 %0, t; }" : "=r"(a) : "l"(p));
    return a;
}
__device__ __forceinline__ float ex2f(float x) {
    float y; asm("ex2.approx.ftz.f32 %0, %1;" : "=f"(y) : "f"(x)); return y;
}
__device__ __forceinline__ void ldsm_x4(uint32_t& r0, uint32_t& r1, uint32_t& r2, uint32_t& r3,
                                        uint32_t addr) {
    asm volatile("ldmatrix.sync.aligned.m8n8.x4.shared.b16 {%0,%1,%2,%3}, [%4];"
                 : "=r"(r0), "=r"(r1), "=r"(r2), "=r"(r3) : "r"(addr));
}
__device__ __forceinline__ void mma16816(float& c0, float& c1, float& c2, float& c3,
                                         uint32_t a0, uint32_t a1, uint32_t a2, uint32_t a3,
                                         uint32_t b0, uint32_t b1) {
    asm volatile(
        "mma.sync.aligned.m16n8k16.row.col.f32.f16.f16.f32 "
        "{%0,%1,%2,%3}, {%4,%5,%6,%7}, {%8,%9}, {%0,%1,%2,%3};"
        : "+f"(c0), "+f"(c1), "+f"(c2), "+f"(c3)
        : "r"(a0), "r"(a1), "r"(a2), "r"(a3), "r"(b0), "r"(b1));
}
#define MBAR_INIT(mbar, cnt) \
    asm volatile("mbarrier.init.shared.b64 [%0], %1;" :: "r"((uint32_t)(mbar)), "r"((uint32_t)(cnt)) : "memory")
#define MBAR_EXPECT_TX(mbar, bytes) \
    asm volatile("mbarrier.arrive.expect_tx.shared.b64 _, [%0], %1;" \
                 :: "r"((uint32_t)(mbar)), "r"((uint32_t)(bytes)) : "memory")
#define BULK_G2S(dst, src, bytes, mbar) \
    asm volatile("cp.async.bulk.shared::cta.global.mbarrier::complete_tx::bytes [%0], [%1], %2, [%3];" \
                 :: "r"((uint32_t)(dst)), "l"(src), "r"((uint32_t)(bytes)), "r"((uint32_t)(mbar)) : "memory")
__device__ __forceinline__ void mbar_wait(uint32_t mbar, uint32_t parity) {
    asm volatile(
        "{\n\t.reg .pred P;\n\t"
        "W%=:\n\t"
        "mbarrier.try_wait.parity.acquire.cta.shared::cta.b64 P, [%0], %1, 0x989680;\n\t"
        "@P bra.uni D%=;\n\t"
        "bra.uni W%=;\n\t"
        "D%=:\n\t}"
        :: "r"(mbar), "r"(parity) : "memory");
}

// ============================ pre-kernel ============================
__global__ void prep_kernel(const float* __restrict__ H1, const float* __restrict__ H2, int n1) {
    int gid = blockIdx.x * blockDim.x + threadIdx.x;
    int row = gid >> 4;
    int q   = gid & 15;                 // float4 chunk: k = 4q..4q+3
    bool isA = row < n1;
    int r = isA ? row : row - n1;
    const float* src = isA ? H1 : H2;
    float4 v = reinterpret_cast<const float4*>(src)[(size_t)r * 16 + q];

    float x[4] = {v.x, v.y, v.z, v.w};
    uint32_t hu[4];
    float ss = 0.f;
    #pragma unroll
    for (int e = 0; e < 4; e++) {
        hu[e] = (uint32_t)__half_as_ushort(__float2half_rn(x[e]));
        ss = fmaf(x[e], x[e], ss);
    }
    uint2 hi = make_uint2(hu[0] | (hu[1] << 16), hu[2] | (hu[3] << 16));

    int ib = r >> 7, lr = r & 127;
    if (!isA) {
        // permute within each 32-row group so lane t's fragment columns are
        // the contiguous actual columns 8t..8t+7.
        int a = lr & 31;
        int l = (((a >> 1) & 3) << 3) | (((a >> 3) & 3) << 1) | (a & 1);
        lr = (lr & ~31) | l;
    }
    int chunk = q >> 1;
    int swc = chunk ^ (lr & 7);               // XOR swizzle for ldmatrix
    size_t off = (size_t)ib * 16384 + (size_t)lr * 128 + swc * 16 + (q & 1) * 8;
    uint8_t* base = isA ? g_H1s : g_H2s;
    *reinterpret_cast<uint2*>(base + off) = hi;

    #pragma unroll
    for (int o = 8; o; o >>= 1) ss += __shfl_xor_sync(0xffffffffu, ss, o, 16);
    if (q == 0) (isA ? g_norm1 : g_norm2)[r] = ss;   // norms in ACTUAL order
}

// ============================ main kernel ============================
#define SM_A    0
#define SM_B    16384
#define SM_N1   32768
#define SM_N2   33280
#define SM_MBAR 33792
#define SM_TOT  33920

__global__ __launch_bounds__(256, 3) void gk_mma(float* __restrict__ out) {
    extern __shared__ uint8_t smem[];
    const uint32_t sb = smem_u32(smem);
    const int tid  = threadIdx.x;
    const int wid  = tid >> 5;
    const int lane = tid & 31;
    const int iT = blockIdx.y * TM;
    const int jT = blockIdx.x * TN;

    // ---- TMA bulk copy of pre-swizzled tile images (16KB + 16KB) ----
    if (tid == 0) MBAR_INIT(sb + SM_MBAR, 1);
    __syncthreads();
    if (tid == 0) {
        MBAR_EXPECT_TX(sb + SM_MBAR, 32768u);
        BULK_G2S(sb + SM_A, g_H1s + (size_t)blockIdx.y * 16384, 16384u, sb + SM_MBAR);
        BULK_G2S(sb + SM_B, g_H2s + (size_t)blockIdx.x * 16384, 16384u, sb + SM_MBAR);
    }
    if (tid < 128) {
        ((float*)(smem + SM_N1))[tid] = g_norm1[iT + tid] * LOG2E;
        ((float*)(smem + SM_N2))[tid] = g_norm2[jT + tid] * LOG2E;
    }
    __syncthreads();
    mbar_wait(sb + SM_MBAR, 0);

    // warp tile: 64 rows x 32 cols.  wr in {0,1}, wc in {0..3}
    const int wr = wid & 1;
    const int wc = wid >> 1;

    // ldmatrix lane addressing
    const uint32_t aKbit = (uint32_t)(lane >> 4);
    const uint32_t bKbit = (uint32_t)((lane >> 3) & 1);
    uint32_t bRow[2], bXor[2];
    #pragma unroll
    for (int ng = 0; ng < 2; ng++) {
        int nb = wc * 32 + ng * 16 + (lane & 7) + ((lane >> 4) & 1) * 8;
        bRow[ng] = sb + SM_B + nb * 128;
        bXor[ng] = (uint32_t)(nb & 7);
    }

    // ---- preload ALL B fragments (4 kc x 2 groups x 4 regs = 32 regs) ----
    uint32_t bF[4][2][4];
    #pragma unroll
    for (int kc = 0; kc < 4; kc++)
        #pragma unroll
        for (int ng = 0; ng < 2; ng++) {
            uint32_t ch = (2u * kc + bKbit) ^ bXor[ng];
            ldsm_x4(bF[kc][ng][0], bF[kc][ng][1], bF[kc][ng][2], bF[kc][ng][3],
                    bRow[ng] + (ch << 4));
        }

    // epilogue lane mapping (B-permuted layout: lane's 8 cols = colb..colb+7)
    const float* n1c = (const float*)(smem + SM_N1);
    const float* n2c = (const float*)(smem + SM_N2);
    const int t  = lane & 3;
    const int g  = lane >> 2;
    const bool hi_g = (g >= 4);
    const int  gl   = g & 3;
    const int colb = wc * 32 + t * 8;

    // ---- per-mi: 4 A-LDSM + 16 HMMA -> 16 acc -> immediate epilogue ----
    #pragma unroll
    for (int mi = 0; mi < 4; mi++) {
        const int ra = wr * 64 + mi * 16 + (lane & 15);
        const uint32_t aBase = sb + SM_A + ra * 128;
        const uint32_t aXr   = (uint32_t)(ra & 7);

        float acc[4][4];
        #pragma unroll
        for (int ni = 0; ni < 4; ni++)
            #pragma unroll
            for (int f = 0; f < 4; f++) acc[ni][f] = 0.f;

        #pragma unroll
        for (int kc = 0; kc < 4; kc++) {
            uint32_t aF[4];
            uint32_t ch = (2u * kc + aKbit) ^ aXr;
            ldsm_x4(aF[0], aF[1], aF[2], aF[3], aBase + (ch << 4));
            #pragma unroll
            for (int ni = 0; ni < 4; ni++)
                mma16816(acc[ni][0], acc[ni][1], acc[ni][2], acc[ni][3],
                         aF[0], aF[1], aF[2], aF[3],
                         bF[kc][ni >> 1][(ni & 1) * 2], bF[kc][ni >> 1][(ni & 1) * 2 + 1]);
        }

        // epilogue for this mi
        const int lr0 = wr * 64 + mi * 16 + g;
        const float rnA = n1c[lr0];
        const float rnB = n1c[lr0 + 8];

        #pragma unroll
        for (int half = 0; half < 2; half++) {
            const float rn = half ? rnB : rnA;
            float4 w0, w1;
            w0.x = ex2f(fmaf(acc[0][half * 2 + 0], 2.f * LOG2E, -rn) - n2c[colb + 0]);
            w0.y = ex2f(fmaf(acc[0][half * 2 + 1], 2.f * LOG2E, -rn) - n2c[colb + 1]);
            w0.z = ex2f(fmaf(acc[1][half * 2 + 0], 2.f * LOG2E, -rn) - n2c[colb + 2]);
            w0.w = ex2f(fmaf(acc[1][half * 2 + 1], 2.f * LOG2E, -rn) - n2c[colb + 3]);
            w1.x = ex2f(fmaf(acc[2][half * 2 + 0], 2.f * LOG2E, -rn) - n2c[colb + 4]);
            w1.y = ex2f(fmaf(acc[2][half * 2 + 1], 2.f * LOG2E, -rn) - n2c[colb + 5]);
            w1.z = ex2f(fmaf(acc[3][half * 2 + 0], 2.f * LOG2E, -rn) - n2c[colb + 6]);
            w1.w = ex2f(fmaf(acc[3][half * 2 + 1], 2.f * LOG2E, -rn) - n2c[colb + 7]);

            // xor(16): swap w1 with g^4 partner -> each STG covers 4 full
            // 128B rows (4 wavefronts, zero write waste).
            float4 w1x;
            w1x.x = __shfl_xor_sync(0xffffffffu, w1.x, 16);
            w1x.y = __shfl_xor_sync(0xffffffffu, w1.y, 16);
            w1x.z = __shfl_xor_sync(0xffffffffu, w1.z, 16);
            w1x.w = __shfl_xor_sync(0xffffffffu, w1.w, 16);

            const int Rbase = iT + wr * 64 + mi * 16 + half * 8;
            {   // rows Rbase..Rbase+3
                float4 v = hi_g ? w1x : w0;
                int col = colb + (hi_g ? 4 : 0);
                __stcs(reinterpret_cast<float4*>(out + (size_t)(Rbase + gl) * NR + jT + col), v);
            }
            {   // rows Rbase+4..Rbase+7
                float4 v = hi_g ? w0 : w1x;
                int col = colb + (hi_g ? 0 : 4);
                __stcs(reinterpret_cast<float4*>(out + (size_t)(Rbase + gl + 4) * NR + jT + col), v);
            }
        }
    }
}

// ============================ launch ============================
extern "C" void kernel_launch(void* const* d_in, const int* in_sizes, int n_in,
                              void* d_out, int out_size)
{
    const float* H1 = (const float*)d_in[0];
    const float* H2 = (const float*)d_in[1];
    float* out = (float*)d_out;

    int n1 = in_sizes[0] / KDIM;   // 8192
    int n2 = in_sizes[1] / KDIM;   // 8192

    prep_kernel<<<(n1 + n2) * 16 / 256, 256>>>(H1, H2, n1);

    static bool attr_set = false;
    if (!attr_set) {
        cudaFuncSetAttribute(gk_mma, cudaFuncAttributeMaxDynamicSharedMemorySize, SM_TOT);
        attr_set = true;
    }
    dim3 grid(n2 / TN, n1 / TM);   // (64, 64)
    gk_mma<<<grid, 256, SM_TOT>>>(out);
}

// round 12
// speedup vs baseline: 1.1591x; 1.0012x over previous
#include <cuda_runtime.h>
#include <cuda_fp16.h>
#include <cstdint>

// out[i,j] = exp(-(||H1_i||^2 + ||H2_j||^2 - 2*H1_i.H2_j)),  H1,H2: [8192,64] f32.
//
// Round 12: R11 + B-fragment reuse across TWO 128-row i-blocks per CTA
// (TM=256). The hoisted B fragments (32 regs, full K) now feed 2x the output,
// halving B-LDSM wavefronts per unit output with zero extra registers.
// Grid 2048 CTAs, 3 CTAs/SM, ~50KB smem.

#define NR    8192
#define KDIM  64
#define TMB   128          // rows per i-block
#define NIB   2            // i-blocks per CTA
#define TN    128
#define LOG2E 1.4426950408889634f

// ---- device scratch: fp16 row images, 128-row blocks of 16KB, pre-swizzled ----
__device__ __align__(1024) uint8_t g_H1s[(size_t)NR * 128];
__device__ __align__(1024) uint8_t g_H2s[(size_t)NR * 128];
__device__ float g_norm1[NR];
__device__ float g_norm2[NR];

// ============================ PTX helpers ============================
__device__ __forceinline__ uint32_t smem_u32(const void* p) {
    uint32_t a;
    asm("{ .reg .u64 t; cvta.to.shared.u64 t, %1; cvt.u32.u64 %0, t; }" : "=r"(a) : "l"(p));
    return a;
}
__device__ __forceinline__ float ex2f(float x) {
    float y; asm("ex2.approx.ftz.f32 %0, %1;" : "=f"(y) : "f"(x)); return y;
}
__device__ __forceinline__ void ldsm_x4(uint32_t& r0, uint32_t& r1, uint32_t& r2, uint32_t& r3,
                                        uint32_t addr) {
    asm volatile("ldmatrix.sync.aligned.m8n8.x4.shared.b16 {%0,%1,%2,%3}, [%4];"
                 : "=r"(r0), "=r"(r1), "=r"(r2), "=r"(r3) : "r"(addr));
}
__device__ __forceinline__ void mma16816(float& c0, float& c1, float& c2, float& c3,
                                         uint32_t a0, uint32_t a1, uint32_t a2, uint32_t a3,
                                         uint32_t b0, uint32_t b1) {
    asm volatile(
        "mma.sync.aligned.m16n8k16.row.col.f32.f16.f16.f32 "
        "{%0,%1,%2,%3}, {%4,%5,%6,%7}, {%8,%9}, {%0,%1,%2,%3};"
        : "+f"(c0), "+f"(c1), "+f"(c2), "+f"(c3)
        : "r"(a0), "r"(a1), "r"(a2), "r"(a3), "r"(b0), "r"(b1));
}
#define MBAR_INIT(mbar, cnt) \
    asm volatile("mbarrier.init.shared.b64 [%0], %1;" :: "r"((uint32_t)(mbar)), "r"((uint32_t)(cnt)) : "memory")
#define MBAR_EXPECT_TX(mbar, bytes) \
    asm volatile("mbarrier.arrive.expect_tx.shared.b64 _, [%0], %1;" \
                 :: "r"((uint32_t)(mbar)), "r"((uint32_t)(bytes)) : "memory")
#define BULK_G2S(dst, src, bytes, mbar) \
    asm volatile("cp.async.bulk.shared::cta.global.mbarrier::complete_tx::bytes [%0], [%1], %2, [%3];" \
                 :: "r"((uint32_t)(dst)), "l"(src), "r"((uint32_t)(bytes)), "r"((uint32_t)(mbar)) : "memory")
__device__ __forceinline__ void mbar_wait(uint32_t mbar, uint32_t parity) {
    asm volatile(
        "{\n\t.reg .pred P;\n\t"
        "W%=:\n\t"
        "mbarrier.try_wait.parity.acquire.cta.shared::cta.b64 P, [%0], %1, 0x989680;\n\t"
        "@P bra.uni D%=;\n\t"
        "bra.uni W%=;\n\t"
        "D%=:\n\t}"
        :: "r"(mbar), "r"(parity) : "memory");
}

// ============================ pre-kernel ============================
__global__ void prep_kernel(const float* __restrict__ H1, const float* __restrict__ H2, int n1) {
    int gid = blockIdx.x * blockDim.x + threadIdx.x;
    int row = gid >> 4;
    int q   = gid & 15;                 // float4 chunk: k = 4q..4q+3
    bool isA = row < n1;
    int r = isA ? row : row - n1;
    const float* src = isA ? H1 : H2;
    float4 v = reinterpret_cast<const float4*>(src)[(size_t)r * 16 + q];

    float x[4] = {v.x, v.y, v.z, v.w};
    uint32_t hu[4];
    float ss = 0.f;
    #pragma unroll
    for (int e = 0; e < 4; e++) {
        hu[e] = (uint32_t)__half_as_ushort(__float2half_rn(x[e]));
        ss = fmaf(x[e], x[e], ss);
    }
    uint2 hi = make_uint2(hu[0] | (hu[1] << 16), hu[2] | (hu[3] << 16));

    int ib = r >> 7, lr = r & 127;
    if (!isA) {
        // permute within each 32-row group so lane t's fragment columns are
        // the contiguous actual columns 8t..8t+7.
        int a = lr & 31;
        int l = (((a >> 1) & 3) << 3) | (((a >> 3) & 3) << 1) | (a & 1);
        lr = (lr & ~31) | l;
    }
    int chunk = q >> 1;
    int swc = chunk ^ (lr & 7);               // XOR swizzle for ldmatrix
    size_t off = (size_t)ib * 16384 + (size_t)lr * 128 + swc * 16 + (q & 1) * 8;
    uint8_t* base = isA ? g_H1s : g_H2s;
    *reinterpret_cast<uint2*>(base + off) = hi;

    #pragma unroll
    for (int o = 8; o; o >>= 1) ss += __shfl_xor_sync(0xffffffffu, ss, o, 16);
    if (q == 0) (isA ? g_norm1 : g_norm2)[r] = ss;   // norms in ACTUAL order
}

// ============================ main kernel ============================
// smem: A blocks 2x16KB | B 16KB | n1 1KB (256) | n2 512B | mbar
#define SM_A    0
#define SM_B    32768
#define SM_N1   49152
#define SM_N2   50176
#define SM_MBAR 50688
#define SM_TOT  50816

__global__ __launch_bounds__(256, 3) void gk_mma(float* __restrict__ out) {
    extern __shared__ uint8_t smem[];
    const uint32_t sb = smem_u32(smem);
    const int tid  = threadIdx.x;
    const int wid  = tid >> 5;
    const int lane = tid & 31;
    const int iT = blockIdx.y * (TMB * NIB);
    const int jT = blockIdx.x * TN;

    // ---- TMA bulk copy: A (2 blocks, 32KB) + B (16KB) ----
    if (tid == 0) MBAR_INIT(sb + SM_MBAR, 1);
    __syncthreads();
    if (tid == 0) {
        MBAR_EXPECT_TX(sb + SM_MBAR, 49152u);
        BULK_G2S(sb + SM_A, g_H1s + (size_t)blockIdx.y * 32768, 32768u, sb + SM_MBAR);
        BULK_G2S(sb + SM_B, g_H2s + (size_t)blockIdx.x * 16384, 16384u, sb + SM_MBAR);
    }
    ((float*)(smem + SM_N1))[tid] = g_norm1[iT + tid] * LOG2E;   // 256 rows
    if (tid < 128)
        ((float*)(smem + SM_N2))[tid] = g_norm2[jT + tid] * LOG2E;
    __syncthreads();
    mbar_wait(sb + SM_MBAR, 0);

    // warp tile: 64 rows x 32 cols per i-block.  wr in {0,1}, wc in {0..3}
    const int wr = wid & 1;
    const int wc = wid >> 1;

    const uint32_t aKbit = (uint32_t)(lane >> 4);
    const uint32_t bKbit = (uint32_t)((lane >> 3) & 1);

    // ---- preload ALL B fragments once (4 kc x 2 groups x 4 regs = 32 regs) ----
    uint32_t bF[4][2][4];
    #pragma unroll
    for (int ng = 0; ng < 2; ng++) {
        int nb = wc * 32 + ng * 16 + (lane & 7) + ((lane >> 4) & 1) * 8;
        uint32_t bRow = sb + SM_B + nb * 128;
        uint32_t bXr  = (uint32_t)(nb & 7);
        #pragma unroll
        for (int kc = 0; kc < 4; kc++) {
            uint32_t ch = (2u * kc + bKbit) ^ bXr;
            ldsm_x4(bF[kc][ng][0], bF[kc][ng][1], bF[kc][ng][2], bF[kc][ng][3],
                    bRow + (ch << 4));
        }
    }

    // epilogue lane mapping (B-permuted layout: lane's 8 cols = colb..colb+7)
    const float* n1c = (const float*)(smem + SM_N1);
    const float* n2c = (const float*)(smem + SM_N2);
    const int t  = lane & 3;
    const int g  = lane >> 2;
    const bool hi_g = (g >= 4);
    const int  gl   = g & 3;
    const int colb = wc * 32 + t * 8;

    // ---- two i-blocks share the hoisted B fragments ----
    #pragma unroll
    for (int ih = 0; ih < NIB; ih++) {
        const uint32_t aBlk = sb + SM_A + ih * 16384;

        #pragma unroll
        for (int mi = 0; mi < 4; mi++) {
            const int ra = wr * 64 + mi * 16 + (lane & 15);
            const uint32_t aBase = aBlk + ra * 128;
            const uint32_t aXr   = (uint32_t)(ra & 7);

            float acc[4][4];
            #pragma unroll
            for (int ni = 0; ni < 4; ni++)
                #pragma unroll
                for (int f = 0; f < 4; f++) acc[ni][f] = 0.f;

            #pragma unroll
            for (int kc = 0; kc < 4; kc++) {
                uint32_t aF[4];
                uint32_t ch = (2u * kc + aKbit) ^ aXr;
                ldsm_x4(aF[0], aF[1], aF[2], aF[3], aBase + (ch << 4));
                #pragma unroll
                for (int ni = 0; ni < 4; ni++)
                    mma16816(acc[ni][0], acc[ni][1], acc[ni][2], acc[ni][3],
                             aF[0], aF[1], aF[2], aF[3],
                             bF[kc][ni >> 1][(ni & 1) * 2], bF[kc][ni >> 1][(ni & 1) * 2 + 1]);
            }

            // epilogue for this (ih, mi)
            const int lrow = ih * 128 + wr * 64 + mi * 16 + g;   // within CTA tile
            const float rnA = n1c[lrow];
            const float rnB = n1c[lrow + 8];

            #pragma unroll
            for (int half = 0; half < 2; half++) {
                const float rn = half ? rnB : rnA;
                float4 w0, w1;
                w0.x = ex2f(fmaf(acc[0][half * 2 + 0], 2.f * LOG2E, -rn) - n2c[colb + 0]);
                w0.y = ex2f(fmaf(acc[0][half * 2 + 1], 2.f * LOG2E, -rn) - n2c[colb + 1]);
                w0.z = ex2f(fmaf(acc[1][half * 2 + 0], 2.f * LOG2E, -rn) - n2c[colb + 2]);
                w0.w = ex2f(fmaf(acc[1][half * 2 + 1], 2.f * LOG2E, -rn) - n2c[colb + 3]);
                w1.x = ex2f(fmaf(acc[2][half * 2 + 0], 2.f * LOG2E, -rn) - n2c[colb + 4]);
                w1.y = ex2f(fmaf(acc[2][half * 2 + 1], 2.f * LOG2E, -rn) - n2c[colb + 5]);
                w1.z = ex2f(fmaf(acc[3][half * 2 + 0], 2.f * LOG2E, -rn) - n2c[colb + 6]);
                w1.w = ex2f(fmaf(acc[3][half * 2 + 1], 2.f * LOG2E, -rn) - n2c[colb + 7]);

                // xor(16): swap w1 with g^4 partner -> each STG covers 4 full
                // 128B rows (4 wavefronts, zero write waste).
                float4 w1x;
                w1x.x = __shfl_xor_sync(0xffffffffu, w1.x, 16);
                w1x.y = __shfl_xor_sync(0xffffffffu, w1.y, 16);
                w1x.z = __shfl_xor_sync(0xffffffffu, w1.z, 16);
                w1x.w = __shfl_xor_sync(0xffffffffu, w1.w, 16);

                const int Rbase = iT + ih * 128 + wr * 64 + mi * 16 + half * 8;
                {   // rows Rbase..Rbase+3
                    float4 v = hi_g ? w1x : w0;
                    int col = colb + (hi_g ? 4 : 0);
                    __stcs(reinterpret_cast<float4*>(out + (size_t)(Rbase + gl) * NR + jT + col), v);
                }
                {   // rows Rbase+4..Rbase+7
                    float4 v = hi_g ? w0 : w1x;
                    int col = colb + (hi_g ? 0 : 4);
                    __stcs(reinterpret_cast<float4*>(out + (size_t)(Rbase + gl + 4) * NR + jT + col), v);
                }
            }
        }
    }
}

// ============================ launch ============================
extern "C" void kernel_launch(void* const* d_in, const int* in_sizes, int n_in,
                              void* d_out, int out_size)
{
    const float* H1 = (const float*)d_in[0];
    const float* H2 = (const float*)d_in[1];
    float* out = (float*)d_out;

    int n1 = in_sizes[0] / KDIM;   // 8192
    int n2 = in_sizes[1] / KDIM;   // 8192

    prep_kernel<<<(n1 + n2) * 16 / 256, 256>>>(H1, H2, n1);

    static bool attr_set = false;
    if (!attr_set) {
        cudaFuncSetAttribute(gk_mma, cudaFuncAttributeMaxDynamicSharedMemorySize, SM_TOT);
        attr_set = true;
    }
    dim3 grid(n2 / TN, n1 / (TMB * NIB));   // (64, 32)
    gk_mma<<<grid, 256, SM_TOT>>>(out);
}